// round 4
// baseline (speedup 1.0000x reference)
#include <cuda_runtime.h>

#define EMBED 1024
#define FFN_DIM 4096
#define VEC4 (EMBED / 4)     // 256 float4 per row
#define EPS 1e-5f
#define ROWS_PER_BLOCK 16

// Scratch (no allocations allowed)
__device__ __align__(16) float d_h[FFN_DIM];    // relu(w2 @ cvec_ffn)
__device__ __align__(16) float d_a[EMBED];      // attn constant vector
__device__ __align__(16) float d_b1f[EMBED];    // ln1_b + w_out @ h

__device__ __forceinline__ void circuit4(const float* __restrict__ p, float* out) {
    float c0 = cosf(p[0]), c1 = cosf(p[1]), c2 = cosf(p[2]), c3 = cosf(p[3]);
    out[0] = c1 * c2 * c3;
    out[1] = c0 * c1;
    out[2] = c0 * c1 * c2;
    out[3] = c0 * c1 * c2 * c3;
}

// kH: blocks 0..15 compute h = relu(w2 @ cvec_f) (4096 elems);
//     blocks 16..143 compute d_a (warp-per-element, 8 e/block * 128 = 1024).
__global__ void __launch_bounds__(256) kH(const float* __restrict__ w_mix,
                                          const float* __restrict__ w2,
                                          const float* __restrict__ attn_p,
                                          const float* __restrict__ ffn_p) {
    const int t = threadIdx.x;
    if (blockIdx.x < 16) {
        float cf[4];
        circuit4(ffn_p, cf);
        int k = blockIdx.x * 256 + t;
        float4 w = reinterpret_cast<const float4*>(w2)[k];   // w2 is [FFN,4]
        d_h[k] = fmaxf(w.x * cf[0] + w.y * cf[1] + w.z * cf[2] + w.w * cf[3], 0.0f);
    } else {
        float ca[4];
        circuit4(attn_p, ca);
        const int warp = t >> 5, lane = t & 31;
        const int e = (blockIdx.x - 16) * 8 + warp;
        const float4* wm = reinterpret_cast<const float4*>(w_mix + (size_t)e * EMBED);
        float sa = 0.0f;
#pragma unroll
        for (int i = 0; i < 8; i++) {
            float4 w = wm[lane + 32 * i];
            sa += w.x * ca[0] + w.y * ca[1] + w.z * ca[2] + w.w * ca[3];
        }
#pragma unroll
        for (int o = 16; o > 0; o >>= 1)
            sa += __shfl_xor_sync(0xffffffffu, sa, o);
        if (lane == 0) d_a[e] = sa;
    }
}

// kF: block-per-element e: d_b1f[e] = ln1_b[e] + w_out[e,:] . h   (h L2-hot)
__global__ void __launch_bounds__(256) kF(const float* __restrict__ w_out,
                                          const float* __restrict__ ln1_b) {
    const int e = blockIdx.x;
    const int t = threadIdx.x;
    const float4* wo = reinterpret_cast<const float4*>(w_out + (size_t)e * FFN_DIM);
    const float4* h4 = reinterpret_cast<const float4*>(d_h);
    float sf = 0.0f;
#pragma unroll
    for (int i = 0; i < 4; i++) {
        float4 w = wo[t + i * 256];
        float4 hv = h4[t + i * 256];
        sf += w.x * hv.x + w.y * hv.y + w.z * hv.z + w.w * hv.w;
    }
#pragma unroll
    for (int o = 16; o > 0; o >>= 1)
        sf += __shfl_xor_sync(0xffffffffu, sf, o);
    __shared__ float sh[8];
    const int warp = t >> 5, lane = t & 31;
    if (lane == 0) sh[warp] = sf;
    __syncthreads();
    if (t == 0) {
        float tot = 0.0f;
#pragma unroll
        for (int i = 0; i < 8; i++) tot += sh[i];
        d_b1f[e] = ln1_b[e] + tot;
    }
}

// kMain: thread owns fixed float4 column; 5 constant float4 in REGISTERS;
// block loops over 16 rows with prefetch; 2 block reductions per row.
// out = g2*(z - m2)*r2 + b2,  z = g1*(x + a - m1)*r1 + b1f
__global__ void __launch_bounds__(256) kMain(const float4* __restrict__ x,
                                             const float4* __restrict__ g1,
                                             const float4* __restrict__ g2,
                                             const float4* __restrict__ b2,
                                             float4* __restrict__ out) {
    const int t = threadIdx.x;
    const int warp = t >> 5, lane = t & 31;
    __shared__ float sm1[16], sm2[16];

    // Constants: 5 float4 = 20 registers, loaded once (L2-hot after wave 1)
    const float4 A  = reinterpret_cast<const float4*>(d_a)[t];
    const float4 G1 = g1[t];
    const float4 B1 = reinterpret_cast<const float4*>(d_b1f)[t];
    const float4 G2 = g2[t];
    const float4 B2 = b2[t];

    const size_t base = (size_t)blockIdx.x * ROWS_PER_BLOCK * VEC4 + t;
    float4 xv = __ldcs(&x[base]);

#pragma unroll
    for (int r = 0; r < ROWS_PER_BLOCK; r++) {
        // u = x + a
        float4 u;
        u.x = xv.x + A.x; u.y = xv.y + A.y; u.z = xv.z + A.z; u.w = xv.w + A.w;

        // prefetch next row while this row reduces
        float4 xn;
        if (r + 1 < ROWS_PER_BLOCK) xn = __ldcs(&x[base + (size_t)(r + 1) * VEC4]);

        // reduction 1
        float s = u.x + u.y + u.z + u.w;
        float q = u.x * u.x + u.y * u.y + u.z * u.z + u.w * u.w;
#pragma unroll
        for (int o = 16; o > 0; o >>= 1) {
            s += __shfl_xor_sync(0xffffffffu, s, o);
            q += __shfl_xor_sync(0xffffffffu, q, o);
        }
        if (lane == 0) { sm1[warp] = s; sm1[8 + warp] = q; }
        __syncthreads();
        float ts = 0.0f, tq = 0.0f;
#pragma unroll
        for (int i = 0; i < 8; i++) { ts += sm1[i]; tq += sm1[8 + i]; }
        float m1 = ts * (1.0f / EMBED);
        float r1 = rsqrtf(tq * (1.0f / EMBED) - m1 * m1 + EPS);

        // z = g1*(u-m1)*r1 + b1f; reduction 2
        float4 z;
        z.x = G1.x * (u.x - m1) * r1 + B1.x;
        z.y = G1.y * (u.y - m1) * r1 + B1.y;
        z.z = G1.z * (u.z - m1) * r1 + B1.z;
        z.w = G1.w * (u.w - m1) * r1 + B1.w;
        s = z.x + z.y + z.z + z.w;
        q = z.x * z.x + z.y * z.y + z.z * z.z + z.w * z.w;
#pragma unroll
        for (int o = 16; o > 0; o >>= 1) {
            s += __shfl_xor_sync(0xffffffffu, s, o);
            q += __shfl_xor_sync(0xffffffffu, q, o);
        }
        if (lane == 0) { sm2[warp] = s; sm2[8 + warp] = q; }
        __syncthreads();
        ts = 0.0f; tq = 0.0f;
#pragma unroll
        for (int i = 0; i < 8; i++) { ts += sm2[i]; tq += sm2[8 + i]; }
        float m2 = ts * (1.0f / EMBED);
        float r2 = rsqrtf(tq * (1.0f / EMBED) - m2 * m2 + EPS);

        // output
        float4 o4;
        o4.x = G2.x * (z.x - m2) * r2 + B2.x;
        o4.y = G2.y * (z.y - m2) * r2 + B2.y;
        o4.z = G2.z * (z.z - m2) * r2 + B2.z;
        o4.w = G2.w * (z.w - m2) * r2 + B2.w;
        __stcs(&out[base + (size_t)r * VEC4], o4);

        xv = xn;
    }
}

extern "C" void kernel_launch(void* const* d_in, const int* in_sizes, int n_in,
                              void* d_out, int out_size) {
    // metadata order: x, wq, wk, wv, w_mix, attn_params, w1, w2, w_out,
    //                 ffn_params, ln1_g, ln1_b, ln2_g, ln2_b
    const float* x      = (const float*)d_in[0];
    const float* w_mix  = (const float*)d_in[4];
    const float* attn_p = (const float*)d_in[5];
    const float* w2     = (const float*)d_in[7];
    const float* w_out  = (const float*)d_in[8];
    const float* ffn_p  = (const float*)d_in[9];
    const float* ln1_g  = (const float*)d_in[10];
    const float* ln1_b  = (const float*)d_in[11];
    const float* ln2_g  = (const float*)d_in[12];
    const float* ln2_b  = (const float*)d_in[13];

    const int n_rows = in_sizes[0] / EMBED;  // B*S = 16384

    kH<<<144, 256>>>(w_mix, w2, attn_p, ffn_p);
    kF<<<EMBED, 256>>>(w_out, ln1_b);
    kMain<<<n_rows / ROWS_PER_BLOCK, 256>>>(
        (const float4*)x,
        (const float4*)ln1_g,
        (const float4*)ln2_g, (const float4*)ln2_b,
        (float4*)d_out);
}